// round 5
// baseline (speedup 1.0000x reference)
#include <cuda_runtime.h>
#include <cuda_bf16.h>
#include <stdint.h>
#include <math.h>

#define CIN  2048
#define CHID 1024
#define CEMB 256
#define BB   4
#define TT   2048

typedef __nv_bfloat16 bf16;

// ---------------- scratch (static device globals; no allocations) ----------
__device__ float g_S1 [(size_t)BB*TT*TT];
__device__ float g_S2 [(size_t)BB*TT*TT];
__device__ float g_Mo [(size_t)BB*TT*TT];

__device__ bf16 g_xh [(size_t)BB*TT*CIN],  g_xl [(size_t)BB*TT*CIN];
__device__ bf16 g_thh[(size_t)CHID*CIN],   g_thl[(size_t)CHID*CIN];
__device__ bf16 g_phh[(size_t)CHID*CIN],   g_phl[(size_t)CHID*CIN];
__device__ bf16 g_gwh[(size_t)CHID*CIN],   g_gwl[(size_t)CHID*CIN];
__device__ bf16 g_wwh[(size_t)CIN*CHID],   g_wwl[(size_t)CIN*CHID];
__device__ bf16 g_ewh[(size_t)CEMB*CIN],   g_ewl[(size_t)CEMB*CIN];

__device__ bf16 g_XTh[(size_t)BB*TT*CHID], g_XTl[(size_t)BB*TT*CHID];
__device__ bf16 g_XPh[(size_t)BB*TT*CHID], g_XPl[(size_t)BB*TT*CHID];
__device__ bf16 g_XGh[(size_t)BB*CHID*TT], g_XGl[(size_t)BB*CHID*TT];
__device__ bf16 g_MTh[(size_t)BB*TT*TT],   g_MTl[(size_t)BB*TT*TT];
__device__ bf16 g_Yh [(size_t)BB*TT*CHID], g_Yl [(size_t)BB*TT*CHID];
__device__ bf16 g_Zh [(size_t)BB*TT*CIN],  g_Zl [(size_t)BB*TT*CIN];

// ---------------- helpers ----------------------------------------------------
__device__ __forceinline__ uint32_t smem_u32(const void* p) {
    uint32_t a;
    asm("{ .reg .u64 t; cvta.to.shared.u64 t, %1; cvt.u32.u64 %0, t; }" : "=r"(a) : "l"(p));
    return a;
}
__device__ __forceinline__ void ldsm4(uint32_t* r, uint32_t addr) {
    asm volatile("ldmatrix.sync.aligned.m8n8.x4.shared.b16 {%0,%1,%2,%3}, [%4];"
        : "=r"(r[0]), "=r"(r[1]), "=r"(r[2]), "=r"(r[3]) : "r"(addr));
}
__device__ __forceinline__ void mma16816(float* c, const uint32_t* a, uint32_t b0, uint32_t b1) {
    asm volatile("mma.sync.aligned.m16n8k16.row.col.f32.bf16.bf16.f32 "
        "{%0,%1,%2,%3}, {%4,%5,%6,%7}, {%8,%9}, {%0,%1,%2,%3};"
        : "+f"(c[0]), "+f"(c[1]), "+f"(c[2]), "+f"(c[3])
        : "r"(a[0]), "r"(a[1]), "r"(a[2]), "r"(a[3]), "r"(b0), "r"(b1));
}
__device__ __forceinline__ void split2(float vx, float vy, uint32_t& h, uint32_t& l) {
    asm("cvt.rn.bf16x2.f32 %0, %1, %2;" : "=r"(h) : "f"(vy), "f"(vx));
    float hx = __uint_as_float(h << 16), hy = __uint_as_float(h & 0xffff0000u);
    asm("cvt.rn.bf16x2.f32 %0, %1, %2;" : "=r"(l) : "f"(vy - hy), "f"(vx - hx));
}
#define CP16(dst, src) asm volatile("cp.async.cg.shared.global [%0], [%1], 16;" :: "r"(dst), "l"(src))
#define CP_COMMIT()    asm volatile("cp.async.commit_group;" ::: "memory")
#define CP_WAIT2()     asm volatile("cp.async.wait_group 2;" ::: "memory")

// ---------------- bf16x3 mma.sync NT GEMM (pre-split operands) ---------------
// C[m,n] = sum_k A[m,k]*B[n,k], A/B given as hi/lo bf16 row-major [rows,K].
// CTA tile 128x128, BK=32, 8 warps (warp 32x64), 4-stage cp.async pipeline.
#define STRIDE_E    40                     // bf16 per smem row (80B, conflict-free ldsm)
#define TILE_B      10240                  // 128*40*2
#define STAGE_BYTES (4*TILE_B)             // Ahi, Alo, Bhi, Blo
#define NSTAGE      4
#define SMEM_TOTAL  (NSTAGE*STAGE_BYTES)   // 163840

__global__ void __launch_bounds__(256, 1)
gemm_mma(const bf16* __restrict__ Ah, const bf16* __restrict__ Al, size_t asb,
         const bf16* __restrict__ Bh, const bf16* __restrict__ Bl, size_t bsb,
         float* __restrict__ C, bf16* __restrict__ Ch, bf16* __restrict__ Cl, size_t csb,
         int N, int K,
         const float* __restrict__ bias_n,
         const float* __restrict__ bias_m,
         const float* __restrict__ addm, size_t addsb)
{
    extern __shared__ char smem[];
    const uint32_t sb = smem_u32(smem);
    const int tid = threadIdx.x, lane = tid & 31, wid = tid >> 5;
    const int bz = blockIdx.z;
    Ah += (size_t)bz * asb;  Al += (size_t)bz * asb;
    Bh += (size_t)bz * bsb;  Bl += (size_t)bz * bsb;
    const int m0 = blockIdx.y * 128, n0 = blockIdx.x * 128;
    const int warpM = wid & 3, warpN = wid >> 2;

    // per-thread cp.async coordinates: two threads per row, 32B each
    const int ldRow0 = tid >> 1;           // rows 0..127
    const int ldSeg0 = (tid & 1) * 2;      // 16B segments {0,1} or {2,3}
    const uint32_t dOff0 = (uint32_t)ldRow0 * 80 + ldSeg0 * 16;

    auto issueStage = [&](int it) {
        const int k0 = it * 32;
        const uint32_t base = sb + (it & (NSTAGE - 1)) * STAGE_BYTES;
        const size_t ar = (size_t)(m0 + ldRow0) * K + k0 + ldSeg0 * 8;
        const size_t br = (size_t)(n0 + ldRow0) * K + k0 + ldSeg0 * 8;
        CP16(base + dOff0,                    Ah + ar);
        CP16(base + dOff0 + 16,               Ah + ar + 8);
        CP16(base + TILE_B + dOff0,           Al + ar);
        CP16(base + TILE_B + dOff0 + 16,      Al + ar + 8);
        CP16(base + 2*TILE_B + dOff0,         Bh + br);
        CP16(base + 2*TILE_B + dOff0 + 16,    Bh + br + 8);
        CP16(base + 3*TILE_B + dOff0,         Bl + br);
        CP16(base + 3*TILE_B + dOff0 + 16,    Bl + br + 8);
        CP_COMMIT();
    };

    float acc[2][8][4] = {};
    const uint32_t aOffB = (uint32_t)((warpM * 32 + (lane & 15)) * STRIDE_E + (lane >> 4) * 8) * 2;
    const uint32_t bOffB = (uint32_t)((warpN * 64 + (lane & 15)) * STRIDE_E + (lane >> 4) * 8) * 2;

    const int nIter = K >> 5;
    issueStage(0); issueStage(1); issueStage(2);

    for (int it = 0; it < nIter; ++it) {
        CP_WAIT2();
        __syncthreads();
        const uint32_t base = sb + (it & (NSTAGE - 1)) * STAGE_BYTES;
        #pragma unroll
        for (int ks = 0; ks < 2; ks++) {
            uint32_t ah[2][4], al[2][4], bh[4][4], bl[4][4];
            #pragma unroll
            for (int mf = 0; mf < 2; mf++) {
                ldsm4(ah[mf], base + aOffB + mf * 1280 + ks * 32);
                ldsm4(al[mf], base + TILE_B + aOffB + mf * 1280 + ks * 32);
            }
            #pragma unroll
            for (int np = 0; np < 4; np++) {
                ldsm4(bh[np], base + 2 * TILE_B + bOffB + np * 1280 + ks * 32);
                ldsm4(bl[np], base + 3 * TILE_B + bOffB + np * 1280 + ks * 32);
            }
            #pragma unroll
            for (int mf = 0; mf < 2; mf++)
                #pragma unroll
                for (int nf = 0; nf < 8; nf++) {
                    const int np = nf >> 1, o = nf & 1;
                    mma16816(acc[mf][nf], ah[mf], bh[np][o], bh[np][2 + o]);
                    mma16816(acc[mf][nf], ah[mf], bl[np][o], bl[np][2 + o]);
                    mma16816(acc[mf][nf], al[mf], bh[np][o], bh[np][2 + o]);
                }
        }
        if (it + 3 < nIter) issueStage(it + 3);
    }

    // ---------------- epilogue ----------------
    const int r = lane >> 2, cq = (lane & 3) * 2;
    #pragma unroll
    for (int mf = 0; mf < 2; mf++) {
        #pragma unroll
        for (int half = 0; half < 2; half++) {
            const int m = m0 + warpM * 32 + mf * 16 + r + half * 8;
            const float bm = bias_m ? bias_m[m] : 0.f;
            #pragma unroll
            for (int nf = 0; nf < 8; nf++) {
                const int gn = n0 + warpN * 64 + nf * 8 + cq;
                float vx = acc[mf][nf][half * 2 + 0] + bm;
                float vy = acc[mf][nf][half * 2 + 1] + bm;
                if (bias_n) { vx += bias_n[gn]; vy += bias_n[gn + 1]; }
                if (addm) {
                    const float2 av = *(const float2*)(addm + (size_t)bz * addsb + (size_t)m * N + gn);
                    vx += av.x; vy += av.y;
                }
                const size_t oi = (size_t)bz * csb + (size_t)m * N + gn;
                if (C) *(float2*)(C + oi) = make_float2(vx, vy);
                if (Ch) {
                    uint32_t h, l;
                    split2(vx, vy, h, l);
                    *(uint32_t*)(Ch + oi) = h;
                    *(uint32_t*)(Cl + oi) = l;
                }
            }
        }
    }
}

// ---------------- elementwise fp32 -> (hi,lo) bf16 ---------------------------
__global__ void convert_split(const float4* __restrict__ in,
                              uint2* __restrict__ hi, uint2* __restrict__ lo, int n4)
{
    int i = blockIdx.x * 256 + threadIdx.x;
    if (i >= n4) return;
    float4 v = in[i];
    uint32_t h0, h1, l0, l1;
    split2(v.x, v.y, h0, l0);
    split2(v.z, v.w, h1, l1);
    hi[i] = make_uint2(h0, h1);
    lo[i] = make_uint2(l0, l1);
}

// ---------------- softmax combine -------------------------------------------
__device__ __forceinline__ float warpMax(float v) {
    #pragma unroll
    for (int o = 16; o > 0; o >>= 1) v = fmaxf(v, __shfl_xor_sync(0xffffffffu, v, o));
    return v;
}
__device__ __forceinline__ float warpSum(float v) {
    #pragma unroll
    for (int o = 16; o > 0; o >>= 1) v += __shfl_xor_sync(0xffffffffu, v, o);
    return v;
}
__device__ __forceinline__ float blockMax(float v, float* sm) {
    v = warpMax(v);
    if ((threadIdx.x & 31) == 0) sm[threadIdx.x >> 5] = v;
    __syncthreads();
    float r = sm[0];
    #pragma unroll
    for (int i = 1; i < 8; i++) r = fmaxf(r, sm[i]);
    __syncthreads();
    return r;
}
__device__ __forceinline__ float blockSum(float v, float* sm) {
    v = warpSum(v);
    if ((threadIdx.x & 31) == 0) sm[threadIdx.x >> 5] = v;
    __syncthreads();
    float r = 0.f;
    #pragma unroll
    for (int i = 0; i < 8; i++) r += sm[i];
    __syncthreads();
    return r;
}

__global__ void combine_softmax(const float* __restrict__ rw, const float* __restrict__ rbp)
{
    __shared__ float sm[8];
    const int t = blockIdx.x;
    const int b = blockIdx.y;
    const float* sa;
    const float* sbp;
    if (b < 2) {
        sa  = g_S1 + ((size_t)(2 * b)     * TT + t) * TT;
        sbp = g_S1 + ((size_t)(2 * b + 1) * TT + t) * TT;
    } else {
        sa  = g_S2 + ((size_t)(2 * b - 4) * TT + t) * TT;
        sbp = g_S2 + ((size_t)(2 * b - 3) * TT + t) * TT;
    }
    const float r0 = rw[0], r1 = rw[1], rc = rbp[0];
    const int tid = threadIdx.x;

    float v1[8], v2[8];
    #pragma unroll
    for (int i = 0; i < 8; i++) { v1[i] = sa[tid + i * 256]; v2[i] = sbp[tid + i * 256]; }

    float m1 = -1e30f, m2 = -1e30f;
    #pragma unroll
    for (int i = 0; i < 8; i++) { m1 = fmaxf(m1, v1[i]); m2 = fmaxf(m2, v2[i]); }
    m1 = blockMax(m1, sm);
    m2 = blockMax(m2, sm);

    float s1 = 0.f, s2 = 0.f;
    #pragma unroll
    for (int i = 0; i < 8; i++) {
        v1[i] = expf(v1[i] - m1); s1 += v1[i];
        v2[i] = expf(v2[i] - m2); s2 += v2[i];
    }
    s1 = blockSum(s1, sm);
    s2 = blockSum(s2, sm);
    const float i1 = 1.f / s1, i2 = 1.f / s2;

    float mm = -1e30f;
    #pragma unroll
    for (int i = 0; i < 8; i++) {
        v1[i] = r0 * v1[i] * i1 + r1 * v2[i] * i2 + rc;
        mm = fmaxf(mm, v1[i]);
    }
    mm = blockMax(mm, sm);

    float s3 = 0.f;
    #pragma unroll
    for (int i = 0; i < 8; i++) { v1[i] = expf(v1[i] - mm); s3 += v1[i]; }
    s3 = blockSum(s3, sm);
    const float i3 = 1.f / s3;

    float* o = g_Mo + ((size_t)b * TT + t) * TT;
    #pragma unroll
    for (int i = 0; i < 8; i++) o[tid + i * 256] = v1[i] * i3;
}

// ---------------- 32x32 transpose with hi/lo split output --------------------
__global__ void transpose_split(const float* __restrict__ in,
                                bf16* __restrict__ oh, bf16* __restrict__ ol)
{
    __shared__ float t[32][33];
    const size_t bo = (size_t)blockIdx.z * TT * TT;
    const int x0 = blockIdx.x * 32, y0 = blockIdx.y * 32;
    const int tx = threadIdx.x, ty = threadIdx.y;
    #pragma unroll
    for (int i = 0; i < 32; i += 8)
        t[ty + i][tx] = in[bo + (size_t)(y0 + ty + i) * TT + x0 + tx];
    __syncthreads();
    #pragma unroll
    for (int i = 0; i < 32; i += 8) {
        const float v = t[tx][ty + i];
        const bf16 h = __float2bfloat16(v);
        const bf16 l = __float2bfloat16(v - __bfloat162float(h));
        const size_t oi = bo + (size_t)(x0 + ty + i) * TT + y0 + tx;
        oh[oi] = h;
        ol[oi] = l;
    }
}

// ---------------- launch -----------------------------------------------------
extern "C" void kernel_launch(void* const* d_in, const int* in_sizes, int n_in,
                              void* d_out, int out_size)
{
    const float* x       = (const float*)d_in[0];
    const float* theta_w = (const float*)d_in[1];
    const float* theta_b = (const float*)d_in[2];
    const float* phi_w   = (const float*)d_in[3];
    const float* phi_b   = (const float*)d_in[4];
    const float* g_w     = (const float*)d_in[5];
    const float* g_b     = (const float*)d_in[6];
    const float* rou_w   = (const float*)d_in[7];
    const float* rou_b   = (const float*)d_in[8];
    const float* w_w     = (const float*)d_in[9];
    const float* w_b     = (const float*)d_in[10];
    const float* emb_w   = (const float*)d_in[11];
    const float* emb_b   = (const float*)d_in[12];
    float* out = (float*)d_out;

    cudaFuncSetAttribute(gemm_mma, cudaFuncAttributeMaxDynamicSharedMemorySize, SMEM_TOTAL);

    float *S1, *S2, *Mo;
    bf16 *xh, *xl, *thh, *thl, *phh, *phl, *gwh, *gwl, *wwh, *wwl, *ewh, *ewl;
    bf16 *XTh, *XTl, *XPh, *XPl, *XGh, *XGl, *MTh, *MTl, *Yh, *Yl, *Zh, *Zl;
    cudaGetSymbolAddress((void**)&S1, g_S1);
    cudaGetSymbolAddress((void**)&S2, g_S2);
    cudaGetSymbolAddress((void**)&Mo, g_Mo);
    cudaGetSymbolAddress((void**)&xh, g_xh);   cudaGetSymbolAddress((void**)&xl, g_xl);
    cudaGetSymbolAddress((void**)&thh, g_thh); cudaGetSymbolAddress((void**)&thl, g_thl);
    cudaGetSymbolAddress((void**)&phh, g_phh); cudaGetSymbolAddress((void**)&phl, g_phl);
    cudaGetSymbolAddress((void**)&gwh, g_gwh); cudaGetSymbolAddress((void**)&gwl, g_gwl);
    cudaGetSymbolAddress((void**)&wwh, g_wwh); cudaGetSymbolAddress((void**)&wwl, g_wwl);
    cudaGetSymbolAddress((void**)&ewh, g_ewh); cudaGetSymbolAddress((void**)&ewl, g_ewl);
    cudaGetSymbolAddress((void**)&XTh, g_XTh); cudaGetSymbolAddress((void**)&XTl, g_XTl);
    cudaGetSymbolAddress((void**)&XPh, g_XPh); cudaGetSymbolAddress((void**)&XPl, g_XPl);
    cudaGetSymbolAddress((void**)&XGh, g_XGh); cudaGetSymbolAddress((void**)&XGl, g_XGl);
    cudaGetSymbolAddress((void**)&MTh, g_MTh); cudaGetSymbolAddress((void**)&MTl, g_MTl);
    cudaGetSymbolAddress((void**)&Yh,  g_Yh);  cudaGetSymbolAddress((void**)&Yl,  g_Yl);
    cudaGetSymbolAddress((void**)&Zh,  g_Zh);  cudaGetSymbolAddress((void**)&Zl,  g_Zl);

    const size_t sX  = (size_t)TT * CIN;
    const size_t sH  = (size_t)TT * CHID;
    const size_t sTT = (size_t)TT * TT;
    const size_t sO  = (size_t)TT * CEMB;

    // pre-split inputs
    auto cvt = [&](const float* src, bf16* h, bf16* l, size_t n) {
        int n4 = (int)(n >> 2);
        convert_split<<<(n4 + 255) / 256, 256>>>((const float4*)src, (uint2*)h, (uint2*)l, n4);
    };
    cvt(x,       xh,  xl,  (size_t)BB * sX);
    cvt(theta_w, thh, thl, (size_t)CHID * CIN);
    cvt(phi_w,   phh, phl, (size_t)CHID * CIN);
    cvt(g_w,     gwh, gwl, (size_t)CHID * CIN);
    cvt(w_w,     wwh, wwl, (size_t)CIN * CHID);
    cvt(emb_w,   ewh, ewl, (size_t)CEMB * CIN);

    // XT = x.theta^T + theta_b  -> hi/lo
    gemm_mma<<<dim3(CHID/128, TT/128, BB), 256, SMEM_TOTAL>>>(
        xh, xl, sX, thh, thl, 0, nullptr, XTh, XTl, sH, CHID, CIN, theta_b, nullptr, nullptr, 0);
    // XP = x.phi^T + phi_b -> hi/lo
    gemm_mma<<<dim3(CHID/128, TT/128, BB), 256, SMEM_TOTAL>>>(
        xh, xl, sX, phh, phl, 0, nullptr, XPh, XPl, sH, CHID, CIN, phi_b, nullptr, nullptr, 0);
    // XGT[h][t] = g_w.x^T + g_b[h] -> hi/lo
    gemm_mma<<<dim3(TT/128, CHID/128, BB), 256, SMEM_TOTAL>>>(
        gwh, gwl, 0, xh, xl, sX, nullptr, XGh, XGl, sH, TT, CIN, nullptr, g_b, nullptr, 0);
    // S1 = x.x^T (fp32)
    gemm_mma<<<dim3(TT/128, TT/128, BB), 256, SMEM_TOTAL>>>(
        xh, xl, sX, xh, xl, sX, S1, nullptr, nullptr, sTT, TT, CIN, nullptr, nullptr, nullptr, 0);
    // S2 = XP.XT^T (fp32)
    gemm_mma<<<dim3(TT/128, TT/128, BB), 256, SMEM_TOTAL>>>(
        XPh, XPl, sH, XTh, XTl, sH, S2, nullptr, nullptr, sTT, TT, CHID, nullptr, nullptr, nullptr, 0);
    // moca (cat/view batch interleave) -> Mo fp32
    combine_softmax<<<dim3(TT, BB), 256>>>(rou_w, rou_b);
    // MoT hi/lo
    transpose_split<<<dim3(TT/32, TT/32, BB), dim3(32, 8)>>>(Mo, MTh, MTl);
    // Y = MoT.XGT^T -> hi/lo
    gemm_mma<<<dim3(CHID/128, TT/128, BB), 256, SMEM_TOTAL>>>(
        MTh, MTl, sTT, XGh, XGl, sH, nullptr, Yh, Yl, sH, CHID, TT, nullptr, nullptr, nullptr, 0);
    // Z = Y.w_w^T + w_b + x -> hi/lo
    gemm_mma<<<dim3(CIN/128, TT/128, BB), 256, SMEM_TOTAL>>>(
        Yh, Yl, sH, wwh, wwl, 0, nullptr, Zh, Zl, sX, CIN, CHID, w_b, nullptr, x, sX);
    // out = Z.emb^T + emb_b (fp32)
    gemm_mma<<<dim3(CEMB/128, TT/128, BB), 256, SMEM_TOTAL>>>(
        Zh, Zl, sX, ewh, ewl, 0, out, nullptr, nullptr, sO, CEMB, CIN, emb_b, nullptr, nullptr, 0);
}